// round 12
// baseline (speedup 1.0000x reference)
#include <cuda_runtime.h>
#include <cstdint>

// ---------------- problem constants ----------------
#define BATCH   4096
#define NF      39
#define ED      16
#define IN_DIM  624     // 39*16
#define NXT     64      // H1/2
#define D1      400
#define D2      400
#define T1      780     // sym pairs h<=m of 39
#define T1P     832     // padded to 13 chunks of 64
#define NCH1    13
#define NCH2    39      // layer-2: chunk c == x0 field m, 64 h per chunk
#define NCHT    52
#define BN_EPS  1e-5f

// power-of-two scaling for fp8 dynamic range (exact in fp)
#define S1INV   (1.f/262144.f)    // 2^-18  (x staged at 2^9 each)
#define SNXT    131072.f          // 2^17   (nxt storage scale)
#define S2INV   (1.f/67108864.f)  // 2^-26  (nxt 2^17 * x 2^9)

// ---------------- scratch (__device__ globals; no runtime alloc) ----------------
__device__ float    g_flat[BATCH * IN_DIM];
__device__ unsigned g_hm1[T1P];              // lo16 = h*16, hi16 = m*16 (word offsets)
// fp8 B-fragments for mma m16n8k32, 16B-aligned for cp.async
__device__ uint4    g_W1f4[NCH1 * 512];
__device__ uint4    g_W2f4[NCH2 * 512];
__device__ float    g_z1[BATCH * D1];
__device__ float    g_z2[BATCH * D2];
__device__ float    g_stats[1600];

// ---------------- cin smem layout (byte offsets, 16B aligned) ----------------
#define OFF_RED  0        // 8 f32
#define OFF_B1   64       // 128 f32
#define OFF_B2   576
#define OFF_OW1  1088     // 64 f32
#define OFF_OW2  1344     // 128 f32
#define OFF_HM   1856     // 832 u32 -> 3328B
#define OFF_X0   5184     // 8*624 f32 (scaled 2^9) = 19968
#define OFF_NXT  25152    // 128 rows x 68 f32 (scaled 2^17) = 34816
#define OFF_P0   59968    // 128 x 80B fp8 = 10240
#define OFF_P1   70208    // 10240
#define OFF_W    80448    // 3 x 8192 (triple buffer)
#define CIN_SM   105024

// ---------------- helpers ----------------
__device__ __forceinline__ unsigned pk_e4m3x4(float f0, float f1, float f2, float f3) {
    unsigned short lo, hi;
    asm("cvt.rn.satfinite.e4m3x2.f32 %0, %1, %2;" : "=h"(lo) : "f"(f1), "f"(f0));
    asm("cvt.rn.satfinite.e4m3x2.f32 %0, %1, %2;" : "=h"(hi) : "f"(f3), "f"(f2));
    unsigned d;
    asm("mov.b32 %0, {%1, %2};" : "=r"(d) : "h"(lo), "h"(hi));
    return d;
}
__device__ __forceinline__ unsigned smem_u32(const void* p) {
    return (unsigned)__cvta_generic_to_shared(p);
}
__device__ __forceinline__ void ldm4(unsigned& a0, unsigned& a1, unsigned& a2, unsigned& a3,
                                     unsigned addr) {
    asm volatile("ldmatrix.sync.aligned.m8n8.x4.shared.b16 {%0,%1,%2,%3}, [%4];"
                 : "=r"(a0), "=r"(a1), "=r"(a2), "=r"(a3) : "r"(addr));
}
__device__ __forceinline__ void mma_fp8(float* c, unsigned a0, unsigned a1, unsigned a2,
                                        unsigned a3, unsigned b0, unsigned b1) {
    asm volatile("mma.sync.aligned.m16n8k32.row.col.f32.e4m3.e4m3.f32 "
                 "{%0,%1,%2,%3},{%4,%5,%6,%7},{%8,%9},{%0,%1,%2,%3};"
                 : "+f"(c[0]), "+f"(c[1]), "+f"(c[2]), "+f"(c[3])
                 : "r"(a0), "r"(a1), "r"(a2), "r"(a3), "r"(b0), "r"(b1));
}
__device__ __forceinline__ void cp_async16(unsigned dst, const void* src) {
    asm volatile("cp.async.cg.shared.global [%0], [%1], 16;" :: "r"(dst), "l"(src));
}
#define CP_COMMIT() asm volatile("cp.async.commit_group;" ::: "memory")
#define CP_WAIT1()  asm volatile("cp.async.wait_group 1;" ::: "memory")

// ---------------- prep kernels ----------------
__global__ void prep_hm() {
    if (threadIdx.x == 0 && blockIdx.x == 0) {
        int t = 0;
        for (int h = 0; h < NF; h++)
            for (int m = h; m < NF; m++)
                g_hm1[t++] = (unsigned)(h * 16) | ((unsigned)(m * 16) << 16);
        for (; t < T1P; t++) g_hm1[t] = 0;
    }
}

__device__ __forceinline__ float w1sym(const float* w1, int o, int t) {
    if (t >= T1) return 0.f;
    unsigned hm = g_hm1[t];
    int h = (hm & 0xffff) >> 4, m = hm >> 20;
    float w = w1[o * (NF * NF) + h * NF + m];
    if (h != m) w += w1[o * (NF * NF) + m * NF + h];
    return w;
}

__global__ void prep_w1f(const float* __restrict__ w1) {
    int tid = blockIdx.x * blockDim.x + threadIdx.x;
    if (tid >= NCH1 * 1024) return;
    int lane = tid & 31, nt = (tid >> 5) & 15, ks = (tid >> 9) & 1, c = tid >> 10;
    int gid = lane >> 2, tig = lane & 3;
    int n = nt * 8 + gid;
    int k0 = c * 64 + ks * 32 + tig * 4;
    uint2 o;
    o.x = pk_e4m3x4(w1sym(w1, n, k0 + 0),  w1sym(w1, n, k0 + 1),
                    w1sym(w1, n, k0 + 2),  w1sym(w1, n, k0 + 3));
    o.y = pk_e4m3x4(w1sym(w1, n, k0 + 16), w1sym(w1, n, k0 + 17),
                    w1sym(w1, n, k0 + 18), w1sym(w1, n, k0 + 19));
    ((uint2*)g_W1f4)[tid] = o;
}

__global__ void prep_w2f(const float* __restrict__ w2) {
    int tid = blockIdx.x * blockDim.x + threadIdx.x;
    if (tid >= NCH2 * 1024) return;
    int lane = tid & 31, nt = (tid >> 5) & 15, ks = (tid >> 9) & 1, c = tid >> 10;
    int gid = lane >> 2, tig = lane & 3;
    int n = nt * 8 + gid;
    int h0 = ks * 32 + tig * 4;
    uint2 o;
    o.x = pk_e4m3x4(w2[(n * NXT + h0 + 0) * NF + c],  w2[(n * NXT + h0 + 1) * NF + c],
                    w2[(n * NXT + h0 + 2) * NF + c],  w2[(n * NXT + h0 + 3) * NF + c]);
    o.y = pk_e4m3x4(w2[(n * NXT + h0 + 16) * NF + c], w2[(n * NXT + h0 + 17) * NF + c],
                    w2[(n * NXT + h0 + 18) * NF + c], w2[(n * NXT + h0 + 19) * NF + c]);
    ((uint2*)g_W2f4)[tid] = o;
}

__global__ void zero_stats() {
    int i = blockIdx.x * blockDim.x + threadIdx.x;
    if (i < 1600) g_stats[i] = 0.f;
}

// ---------------- gather + linear part (writes base of out) ----------------
__global__ void gather_linear(const int* __restrict__ fi, const float* __restrict__ emb,
                              const float* __restrict__ lw, const float* __restrict__ lb,
                              const float* __restrict__ ow, const float* __restrict__ ob,
                              float* __restrict__ out) {
    int b    = blockIdx.x * 8 + (threadIdx.x >> 5);
    int lane = threadIdx.x & 31;
    float acc = 0.f;
    for (int j = lane; j < IN_DIM; j += 32) {
        int f = j >> 4, d = j & 15;
        int idx = fi[b * NF + f];
        float v = emb[(size_t)idx * ED + d];
        g_flat[b * IN_DIM + j] = v;
        acc += v * lw[j];
    }
    #pragma unroll
    for (int s = 16; s; s >>= 1) acc += __shfl_xor_sync(0xffffffffu, acc, s);
    if (lane == 0) out[b] = (acc + lb[0]) * ow[0] + ob[0];
}

// ---------------- CIN fp8, software-pipelined: cp.async W (dist 2, 3-buf), ------
// ---------------- double-buffered P, one barrier per chunk ----------------------
__global__ __launch_bounds__(256, 2) void cin_fp8(const float* __restrict__ b1,
                                                  const float* __restrict__ b2,
                                                  const float* __restrict__ ow,
                                                  float* __restrict__ out) {
    extern __shared__ char smem[];
    const unsigned sbase = smem_u32(smem);
    float*          red  = (float*)(smem + OFF_RED);
    float*          b1s  = (float*)(smem + OFF_B1);
    float*          b2s  = (float*)(smem + OFF_B2);
    float*          ow1v = (float*)(smem + OFF_OW1);
    float*          ow2v = (float*)(smem + OFF_OW2);
    unsigned*       hmw  = (unsigned*)(smem + OFF_HM);
    float*          x0s  = (float*)(smem + OFF_X0);
    float*          nxts = (float*)(smem + OFF_NXT);

    const int tid = threadIdx.x, wid = tid >> 5, lane = tid & 31;
    const int wm = wid >> 1, wn = wid & 1;          // 4 M-warps x 2 N-warps
    const int gid = lane >> 2, tig = lane & 3;
    const int b0 = blockIdx.x * 8;

    {   // stage inputs; x0 scaled by 2^9 for fp8 range
        const float4* src = (const float4*)&g_flat[(size_t)b0 * IN_DIM];
        float4* dst = (float4*)x0s;
        for (int j = tid; j < 8 * IN_DIM / 4; j += 256) {
            float4 v = src[j];
            v.x *= 512.f; v.y *= 512.f; v.z *= 512.f; v.w *= 512.f;
            dst[j] = v;
        }
        for (int j = tid; j < T1P; j += 256) hmw[j] = g_hm1[j];
        if (tid < 128) { b1s[tid] = b1[tid]; b2s[tid] = b2[tid]; ow2v[tid] = ow[65 + tid]; }
        if (tid < 64) ow1v[tid] = ow[1 + tid];
        if (tid < 8) red[tid] = 0.f;
    }

    const int row = tid >> 1, half = tid & 1;       // P-build mapping: 2 threads per row
    const int bb = row >> 4, dd = row & 15;
    const float* xb = x0s + bb * IN_DIM + dd;       // element at xb[h*16]

    // ldmatrix lane address offset within a P buffer
    const int mi = lane >> 3, r7 = lane & 7;
    const unsigned rowsel = (unsigned)((wm * 32 + (mi & 1) * 8 + r7) * 80 + (mi >> 1) * 16);
    const unsigned pbase[2] = { sbase + OFF_P0 + rowsel, sbase + OFF_P1 + rowsel };
    char* const   pdst[2]  = { smem + OFF_P0 + row * 80 + half * 32,
                               smem + OFF_P1 + row * 80 + half * 32 };
    const unsigned wbase = sbase + OFF_W;

    float acc[2][8][4];

    // ---- pipeline primitives ----
    auto prefW = [&](const uint4* chunk_src, int g) {
        unsigned dst = wbase + (unsigned)(g % 3) * 8192u + (unsigned)tid * 16u;
        cp_async16(dst, chunk_src + tid);
        cp_async16(dst + 4096u, chunk_src + 256 + tid);
        CP_COMMIT();
    };
    auto buildP1 = [&](int c, char* dst) {
        int tb = c * 64 + half * 32;
        unsigned u[8];
        #pragma unroll
        for (int g = 0; g < 8; g++) {
            unsigned m0 = hmw[tb + 4 * g],     m1 = hmw[tb + 4 * g + 1];
            unsigned m2 = hmw[tb + 4 * g + 2], m3 = hmw[tb + 4 * g + 3];
            u[g] = pk_e4m3x4(xb[m0 & 0xffff] * xb[m0 >> 16],
                             xb[m1 & 0xffff] * xb[m1 >> 16],
                             xb[m2 & 0xffff] * xb[m2 >> 16],
                             xb[m3 & 0xffff] * xb[m3 >> 16]);
        }
        ((uint4*)dst)[0] = make_uint4(u[0], u[1], u[2], u[3]);
        ((uint4*)dst)[1] = make_uint4(u[4], u[5], u[6], u[7]);
    };
    const float* nr = nxts + row * 68 + half * 32;
    auto buildP2 = [&](int c2, char* dst) {
        float xv = x0s[bb * IN_DIM + c2 * 16 + dd];
        unsigned u[8];
        #pragma unroll
        for (int g = 0; g < 8; g++) {
            float4 nv = *(const float4*)(nr + 4 * g);
            u[g] = pk_e4m3x4(nv.x * xv, nv.y * xv, nv.z * xv, nv.w * xv);
        }
        ((uint4*)dst)[0] = make_uint4(u[0], u[1], u[2], u[3]);
        ((uint4*)dst)[1] = make_uint4(u[4], u[5], u[6], u[7]);
    };
    auto mmaChunk = [&](int g) {
        const uint2* Wc2 = (const uint2*)(smem + OFF_W + (g % 3) * 8192);
        unsigned pb = pbase[g & 1];
        #pragma unroll
        for (int ks = 0; ks < 2; ks++) {
            unsigned bf[8][2];
            #pragma unroll
            for (int nf = 0; nf < 8; nf++) {
                uint2 w = Wc2[(ks * 16 + wn * 8 + nf) * 32 + lane];
                bf[nf][0] = w.x; bf[nf][1] = w.y;
            }
            #pragma unroll
            for (int fm = 0; fm < 2; fm++) {
                unsigned a0, a1, a2, a3;
                ldm4(a0, a1, a2, a3, pb + (unsigned)(fm * 16 * 80 + ks * 32));
                #pragma unroll
                for (int nf = 0; nf < 8; nf++)
                    mma_fp8(acc[fm][nf], a0, a1, a2, a3, bf[nf][0], bf[nf][1]);
            }
        }
    };

    // ---- preload W(0), W(1); staging must be visible before P build reads x0s ----
    prefW(g_W1f4, 0);
    prefW(g_W1f4 + 512, 1);
    __syncthreads();          // x0s/hmw staging visible
    buildP1(0, pdst[0]);
    CP_WAIT1();               // W(0) complete
    __syncthreads();          // P(0) visible

    // ================= LAYER 1 (g = 0..12) =================
    #pragma unroll
    for (int fm = 0; fm < 2; fm++)
        #pragma unroll
        for (int nf = 0; nf < 8; nf++)
            #pragma unroll
            for (int q = 0; q < 4; q++) acc[fm][nf][q] = 0.f;

    for (int c = 0; c < NCH1; c++) {
        mmaChunk(c);
        if (c < NCH1 - 1) buildP1(c + 1, pdst[(c + 1) & 1]);
        {   // prefetch g=c+2 (spills into layer-2 chunks 0,1)
            int g2 = c + 2;
            if (g2 < NCH1) prefW(g_W1f4 + g2 * 512, g2);
            else prefW(g_W2f4 + (g2 - NCH1) * 512, g2);
        }
        CP_WAIT1();
        __syncthreads();
    }

    // ---- layer-1 epilogue: cols 0..63 -> nxt (f32 scaled 2^17); 64..127 -> hi1 dot ----
    if (wn == 0) {
        #pragma unroll
        for (int fm = 0; fm < 2; fm++) {
            int r0 = wm * 32 + fm * 16 + gid;
            #pragma unroll
            for (int nf = 0; nf < 8; nf++) {
                int o0 = nf * 8 + tig * 2;
                nxts[r0 * 68 + o0]           = fmaxf(acc[fm][nf][0] * S1INV + b1s[o0], 0.f) * SNXT;
                nxts[r0 * 68 + o0 + 1]       = fmaxf(acc[fm][nf][1] * S1INV + b1s[o0 + 1], 0.f) * SNXT;
                nxts[(r0 + 8) * 68 + o0]     = fmaxf(acc[fm][nf][2] * S1INV + b1s[o0], 0.f) * SNXT;
                nxts[(r0 + 8) * 68 + o0 + 1] = fmaxf(acc[fm][nf][3] * S1INV + b1s[o0 + 1], 0.f) * SNXT;
            }
        }
    } else {
        #pragma unroll
        for (int fm = 0; fm < 2; fm++) {
            float s = 0.f;
            #pragma unroll
            for (int nf = 0; nf < 8; nf++) {
                int oo = nf * 8 + tig * 2;          // global o = 64+oo
                s += fmaxf(acc[fm][nf][0] * S1INV + b1s[64 + oo], 0.f) * ow1v[oo];
                s += fmaxf(acc[fm][nf][1] * S1INV + b1s[64 + oo + 1], 0.f) * ow1v[oo + 1];
                s += fmaxf(acc[fm][nf][2] * S1INV + b1s[64 + oo], 0.f) * ow1v[oo];
                s += fmaxf(acc[fm][nf][3] * S1INV + b1s[64 + oo + 1], 0.f) * ow1v[oo + 1];
            }
            #pragma unroll
            for (int sh = 16; sh; sh >>= 1) s += __shfl_xor_sync(0xffffffffu, s, sh);
            if (lane == 0) atomicAdd(&red[wm * 2 + fm], s);
        }
    }
    __syncthreads();          // nxts visible

    // ================= LAYER 2 (g = 13..51; chunk c2 == x0 field m) =================
    #pragma unroll
    for (int fm = 0; fm < 2; fm++)
        #pragma unroll
        for (int nf = 0; nf < 8; nf++)
            #pragma unroll
            for (int q = 0; q < 4; q++) acc[fm][nf][q] = 0.f;

    buildP2(0, pdst[NCH1 & 1]);
    __syncthreads();          // P2(0) visible; W(13) completed during layer-1 tail

    for (int c2 = 0; c2 < NCH2; c2++) {
        int g = NCH1 + c2;
        mmaChunk(g);
        if (c2 < NCH2 - 1) buildP2(c2 + 1, pdst[(g + 1) & 1]);
        if (c2 + 2 < NCH2) prefW(g_W2f4 + (c2 + 2) * 512, g + 2);
        else CP_COMMIT();     // keep the group count flowing for WAIT1
        CP_WAIT1();
        __syncthreads();
    }

    // ---- layer-2 epilogue: relu + dot ow[65..193) ----
    #pragma unroll
    for (int fm = 0; fm < 2; fm++) {
        float s = 0.f;
        #pragma unroll
        for (int nf = 0; nf < 8; nf++) {
            int o = wn * 64 + nf * 8 + tig * 2;
            s += fmaxf(acc[fm][nf][0] * S2INV + b2s[o], 0.f) * ow2v[o];
            s += fmaxf(acc[fm][nf][1] * S2INV + b2s[o + 1], 0.f) * ow2v[o + 1];
            s += fmaxf(acc[fm][nf][2] * S2INV + b2s[o], 0.f) * ow2v[o];
            s += fmaxf(acc[fm][nf][3] * S2INV + b2s[o + 1], 0.f) * ow2v[o + 1];
        }
        #pragma unroll
        for (int sh = 16; sh; sh >>= 1) s += __shfl_xor_sync(0xffffffffu, s, sh);
        if (lane == 0) atomicAdd(&red[wm * 2 + fm], s);
    }
    __syncthreads();
    if (tid < 8) atomicAdd(&out[b0 + tid], red[tid]);
}

// ---------------- deep-tower GEMM (64x64 tile, BN-on-load, stats epilogue) ----------------
__global__ __launch_bounds__(256) void gemm_deep(const float* __restrict__ A, int lda,
                                                 const float* __restrict__ B, int ldb,
                                                 const float* __restrict__ bias,
                                                 float* __restrict__ C, int K, int N,
                                                 int use_bn, const float* __restrict__ statsIn,
                                                 const float* __restrict__ bng,
                                                 const float* __restrict__ bnb,
                                                 float* __restrict__ statsOut) {
    __shared__ float As[16][68];
    __shared__ float Bs[16][68];
    __shared__ float bnsc[D1], bnsh[D1];

    int tx = threadIdx.x & 15, ty = threadIdx.x >> 4;
    int m0 = blockIdx.y * 64, n0 = blockIdx.x * 64;

    if (use_bn) {
        for (int k = threadIdx.x; k < K; k += 256) {
            float mean = statsIn[k] * (1.f / BATCH);
            float var  = statsIn[400 + k] * (1.f / BATCH) - mean * mean;
            float sc = bng[k] * rsqrtf(var + BN_EPS);
            bnsc[k] = sc; bnsh[k] = bnb[k] - mean * sc;
        }
        __syncthreads();
    }

    float accr[4][4];
    #pragma unroll
    for (int i = 0; i < 4; i++)
        #pragma unroll
        for (int j = 0; j < 4; j++) accr[i][j] = 0.f;

    for (int k0 = 0; k0 < K; k0 += 16) {
        {
            int rw = threadIdx.x >> 2;
            int kq = (threadIdx.x & 3) * 4;
            float4 v = *(const float4*)&A[(size_t)(m0 + rw) * lda + k0 + kq];
            if (use_bn) {
                v.x = fmaxf(v.x * bnsc[k0 + kq + 0] + bnsh[k0 + kq + 0], 0.f);
                v.y = fmaxf(v.y * bnsc[k0 + kq + 1] + bnsh[k0 + kq + 1], 0.f);
                v.z = fmaxf(v.z * bnsc[k0 + kq + 2] + bnsh[k0 + kq + 2], 0.f);
                v.w = fmaxf(v.w * bnsc[k0 + kq + 3] + bnsh[k0 + kq + 3], 0.f);
            }
            As[kq + 0][rw] = v.x; As[kq + 1][rw] = v.y;
            As[kq + 2][rw] = v.z; As[kq + 3][rw] = v.w;
        }
        {
            int kk = threadIdx.x >> 4;
            int nq = (threadIdx.x & 15) * 4;
            int n  = n0 + nq;
            float4 v = make_float4(0.f, 0.f, 0.f, 0.f);
            if (n < N) v = *(const float4*)&B[(size_t)(k0 + kk) * ldb + n];
            *(float4*)&Bs[kk][nq] = v;
        }
        __syncthreads();
        #pragma unroll
        for (int kk = 0; kk < 16; kk++) {
            float4 a  = *(const float4*)&As[kk][ty * 4];
            float4 bv = *(const float4*)&Bs[kk][tx * 4];
            float al[4] = {a.x, a.y, a.z, a.w};
            float bl[4] = {bv.x, bv.y, bv.z, bv.w};
            #pragma unroll
            for (int i = 0; i < 4; i++)
                #pragma unroll
                for (int j = 0; j < 4; j++) accr[i][j] += al[i] * bl[j];
        }
        __syncthreads();
    }

    float colsum[4] = {0.f, 0.f, 0.f, 0.f};
    float colsq[4]  = {0.f, 0.f, 0.f, 0.f};
    #pragma unroll
    for (int j = 0; j < 4; j++) {
        int n = n0 + tx * 4 + j;
        float bj = (n < N) ? bias[n] : 0.f;
        #pragma unroll
        for (int i = 0; i < 4; i++) {
            int rw = m0 + ty * 4 + i;
            float v = accr[i][j] + bj;
            if (n < N) C[(size_t)rw * N + n] = v;
            colsum[j] += v;
            colsq[j]  += v * v;
        }
    }
    __syncthreads();
    #pragma unroll
    for (int j = 0; j < 4; j++) As[ty][tx * 4 + j] = colsum[j];
    __syncthreads();
    if (threadIdx.x < 64) {
        float s = 0.f;
        #pragma unroll
        for (int r = 0; r < 16; r++) s += As[r][threadIdx.x];
        int n = n0 + threadIdx.x;
        if (n < N) atomicAdd(&statsOut[n], s);
    }
    __syncthreads();
    #pragma unroll
    for (int j = 0; j < 4; j++) As[ty][tx * 4 + j] = colsq[j];
    __syncthreads();
    if (threadIdx.x < 64) {
        float s = 0.f;
        #pragma unroll
        for (int r = 0; r < 16; r++) s += As[r][threadIdx.x];
        int n = n0 + threadIdx.x;
        if (n < N) atomicAdd(&statsOut[400 + n], s);
    }
}

// ---------------- final: BN2 + relu + dot with out_w deep segment ----------------
__global__ void final_deep(const float* __restrict__ bng2, const float* __restrict__ bnb2,
                           const float* __restrict__ ow, float* __restrict__ out) {
    __shared__ float sc[D2], sh[D2];
    for (int k = threadIdx.x; k < D2; k += 256) {
        float mean = g_stats[800 + k] * (1.f / BATCH);
        float var  = g_stats[1200 + k] * (1.f / BATCH) - mean * mean;
        float s = bng2[k] * rsqrtf(var + BN_EPS);
        sc[k] = s; sh[k] = bnb2[k] - mean * s;
    }
    __syncthreads();
    int b    = blockIdx.x * 8 + (threadIdx.x >> 5);
    int lane = threadIdx.x & 31;
    float acc = 0.f;
    for (int k = lane; k < D2; k += 32) {
        float v = fmaxf(g_z2[b * D2 + k] * sc[k] + sh[k], 0.f);
        acc += v * ow[1 + 192 + k];
    }
    #pragma unroll
    for (int s = 16; s; s >>= 1) acc += __shfl_xor_sync(0xffffffffu, acc, s);
    if (lane == 0) atomicAdd(&out[b], acc);
}

// ---------------- launcher: single stream (graph-capture safe) ----------------
extern "C" void kernel_launch(void* const* d_in, const int* in_sizes, int n_in,
                              void* d_out, int out_size) {
    const int*   fi  = (const int*)  d_in[0];
    const float* emb = (const float*)d_in[2];
    const float* lw  = (const float*)d_in[3];
    const float* lb  = (const float*)d_in[4];
    const float* w1  = (const float*)d_in[5];
    const float* cb1 = (const float*)d_in[6];
    const float* w2  = (const float*)d_in[7];
    const float* cb2 = (const float*)d_in[8];
    const float* dw1 = (const float*)d_in[9];
    const float* db1 = (const float*)d_in[10];
    const float* bg1 = (const float*)d_in[11];
    const float* bb1 = (const float*)d_in[12];
    const float* dw2 = (const float*)d_in[13];
    const float* db2 = (const float*)d_in[14];
    const float* bg2 = (const float*)d_in[15];
    const float* bb2 = (const float*)d_in[16];
    const float* ow  = (const float*)d_in[17];
    const float* ob  = (const float*)d_in[18];
    float* out = (float*)d_out;

    float* z1p; cudaGetSymbolAddress((void**)&z1p, g_z1);
    float* z2p; cudaGetSymbolAddress((void**)&z2p, g_z2);
    float* flatp; cudaGetSymbolAddress((void**)&flatp, g_flat);
    float* statsp; cudaGetSymbolAddress((void**)&statsp, g_stats);

    cudaFuncSetAttribute(cin_fp8, cudaFuncAttributeMaxDynamicSharedMemorySize, CIN_SM);

    prep_hm<<<1, 32>>>();
    prep_w1f<<<(NCH1 * 1024 + 255) / 256, 256>>>(w1);
    prep_w2f<<<(NCH2 * 1024 + 255) / 256, 256>>>(w2);
    zero_stats<<<7, 256>>>();

    gather_linear<<<BATCH / 8, 256>>>(fi, emb, lw, lb, ow, ob, out);

    cin_fp8<<<BATCH / 8, 256, CIN_SM>>>(cb1, cb2, ow, out);

    gemm_deep<<<dim3((D1 + 63) / 64, BATCH / 64), 256>>>(
        flatp, IN_DIM, dw1, D1, db1, z1p, IN_DIM, D1,
        0, nullptr, nullptr, nullptr, statsp);

    gemm_deep<<<dim3((D2 + 63) / 64, BATCH / 64), 256>>>(
        z1p, D1, dw2, D2, db2, z2p, D1, D2,
        1, statsp, bg1, bb1, statsp + 800);

    final_deep<<<BATCH / 8, 256>>>(bg2, bb2, ow, out);
}

// round 13
// speedup vs baseline: 1.0017x; 1.0017x over previous
#include <cuda_runtime.h>
#include <cstdint>

// ---------------- problem constants ----------------
#define BATCH   4096
#define NF      39
#define ED      16
#define IN_DIM  624     // 39*16
#define NXT     64      // H1/2
#define D1      400
#define D2      400
#define T1      780     // sym pairs h<=m of 39
#define T1P     832     // padded to 13 chunks of 64
#define NCH1    13
#define NCH2    39      // layer-2: chunk c == x0 field m, 64 h per chunk
#define NCHT    52
#define BN_EPS  1e-5f

// power-of-two scaling for fp8 dynamic range (exact in fp)
#define S1INV   (1.f/262144.f)    // 2^-18  (x staged at 2^9 each)
#define SNXT    131072.f          // 2^17   (nxt storage scale)
#define S2INV   (1.f/67108864.f)  // 2^-26  (nxt 2^17 * x 2^9)

// ---------------- scratch (__device__ globals; no runtime alloc) ----------------
__device__ float    g_flat[BATCH * IN_DIM];
__device__ unsigned g_hm1[T1P];              // lo16 = h*16, hi16 = m*16 (word offsets)
// fp8 B-fragments for mma m16n8k32, 16B-aligned for cp.async
__device__ uint4    g_W1f4[NCH1 * 512];
__device__ uint4    g_W2f4[NCH2 * 512];
__device__ float    g_z1[BATCH * D1];
__device__ float    g_z2[BATCH * D2];
__device__ float    g_stats[1600];

// ---------------- cin smem layout (byte offsets, 16B aligned) ----------------
#define OFF_RED  0        // 8 f32
#define OFF_B1   64       // 128 f32
#define OFF_B2   576
#define OFF_OW1  1088     // 64 f32
#define OFF_OW2  1344     // 128 f32
#define OFF_HM   1856     // 832 u32 -> 3328B
#define OFF_X0   5184     // 8*624 f32 (scaled 2^9) = 19968
#define OFF_NXT  25152    // 128 rows x 68 f32 (scaled 2^17) = 34816
#define OFF_P0   59968    // 128 x 80B fp8 = 10240
#define OFF_P1   70208    // 10240
#define OFF_W    80448    // 3 x 8192 (triple buffer)
#define CIN_SM   105024

// ---------------- helpers ----------------
__device__ __forceinline__ unsigned pk_e4m3x4(float f0, float f1, float f2, float f3) {
    unsigned short lo, hi;
    asm("cvt.rn.satfinite.e4m3x2.f32 %0, %1, %2;" : "=h"(lo) : "f"(f1), "f"(f0));
    asm("cvt.rn.satfinite.e4m3x2.f32 %0, %1, %2;" : "=h"(hi) : "f"(f3), "f"(f2));
    unsigned d;
    asm("mov.b32 %0, {%1, %2};" : "=r"(d) : "h"(lo), "h"(hi));
    return d;
}
__device__ __forceinline__ unsigned smem_u32(const void* p) {
    return (unsigned)__cvta_generic_to_shared(p);
}
__device__ __forceinline__ void ldm4(unsigned& a0, unsigned& a1, unsigned& a2, unsigned& a3,
                                     unsigned addr) {
    asm volatile("ldmatrix.sync.aligned.m8n8.x4.shared.b16 {%0,%1,%2,%3}, [%4];"
                 : "=r"(a0), "=r"(a1), "=r"(a2), "=r"(a3) : "r"(addr));
}
__device__ __forceinline__ void mma_fp8(float* c, unsigned a0, unsigned a1, unsigned a2,
                                        unsigned a3, unsigned b0, unsigned b1) {
    asm volatile("mma.sync.aligned.m16n8k32.row.col.f32.e4m3.e4m3.f32 "
                 "{%0,%1,%2,%3},{%4,%5,%6,%7},{%8,%9},{%0,%1,%2,%3};"
                 : "+f"(c[0]), "+f"(c[1]), "+f"(c[2]), "+f"(c[3])
                 : "r"(a0), "r"(a1), "r"(a2), "r"(a3), "r"(b0), "r"(b1));
}
__device__ __forceinline__ void cp_async16(unsigned dst, const void* src) {
    asm volatile("cp.async.cg.shared.global [%0], [%1], 16;" :: "r"(dst), "l"(src));
}
#define CP_COMMIT() asm volatile("cp.async.commit_group;" ::: "memory")
#define CP_WAIT1()  asm volatile("cp.async.wait_group 1;" ::: "memory")

// ---------------- prep kernels ----------------
__global__ void prep_hm() {
    if (threadIdx.x == 0 && blockIdx.x == 0) {
        int t = 0;
        for (int h = 0; h < NF; h++)
            for (int m = h; m < NF; m++)
                g_hm1[t++] = (unsigned)(h * 16) | ((unsigned)(m * 16) << 16);
        for (; t < T1P; t++) g_hm1[t] = 0;
    }
}

__device__ __forceinline__ float w1sym(const float* w1, int o, int t) {
    if (t >= T1) return 0.f;
    unsigned hm = g_hm1[t];
    int h = (hm & 0xffff) >> 4, m = hm >> 20;
    float w = w1[o * (NF * NF) + h * NF + m];
    if (h != m) w += w1[o * (NF * NF) + m * NF + h];
    return w;
}

__global__ void prep_w1f(const float* __restrict__ w1) {
    int tid = blockIdx.x * blockDim.x + threadIdx.x;
    if (tid >= NCH1 * 1024) return;
    int lane = tid & 31, nt = (tid >> 5) & 15, ks = (tid >> 9) & 1, c = tid >> 10;
    int gid = lane >> 2, tig = lane & 3;
    int n = nt * 8 + gid;
    int k0 = c * 64 + ks * 32 + tig * 4;
    uint2 o;
    o.x = pk_e4m3x4(w1sym(w1, n, k0 + 0),  w1sym(w1, n, k0 + 1),
                    w1sym(w1, n, k0 + 2),  w1sym(w1, n, k0 + 3));
    o.y = pk_e4m3x4(w1sym(w1, n, k0 + 16), w1sym(w1, n, k0 + 17),
                    w1sym(w1, n, k0 + 18), w1sym(w1, n, k0 + 19));
    ((uint2*)g_W1f4)[tid] = o;
}

__global__ void prep_w2f(const float* __restrict__ w2) {
    int tid = blockIdx.x * blockDim.x + threadIdx.x;
    if (tid >= NCH2 * 1024) return;
    int lane = tid & 31, nt = (tid >> 5) & 15, ks = (tid >> 9) & 1, c = tid >> 10;
    int gid = lane >> 2, tig = lane & 3;
    int n = nt * 8 + gid;
    int h0 = ks * 32 + tig * 4;
    uint2 o;
    o.x = pk_e4m3x4(w2[(n * NXT + h0 + 0) * NF + c],  w2[(n * NXT + h0 + 1) * NF + c],
                    w2[(n * NXT + h0 + 2) * NF + c],  w2[(n * NXT + h0 + 3) * NF + c]);
    o.y = pk_e4m3x4(w2[(n * NXT + h0 + 16) * NF + c], w2[(n * NXT + h0 + 17) * NF + c],
                    w2[(n * NXT + h0 + 18) * NF + c], w2[(n * NXT + h0 + 19) * NF + c]);
    ((uint2*)g_W2f4)[tid] = o;
}

__global__ void zero_stats() {
    int i = blockIdx.x * blockDim.x + threadIdx.x;
    if (i < 1600) g_stats[i] = 0.f;
}

// ---------------- gather + linear part (writes base of out) ----------------
__global__ void gather_linear(const int* __restrict__ fi, const float* __restrict__ emb,
                              const float* __restrict__ lw, const float* __restrict__ lb,
                              const float* __restrict__ ow, const float* __restrict__ ob,
                              float* __restrict__ out) {
    int b    = blockIdx.x * 8 + (threadIdx.x >> 5);
    int lane = threadIdx.x & 31;
    float acc = 0.f;
    for (int j = lane; j < IN_DIM; j += 32) {
        int f = j >> 4, d = j & 15;
        int idx = fi[b * NF + f];
        float v = emb[(size_t)idx * ED + d];
        g_flat[b * IN_DIM + j] = v;
        acc += v * lw[j];
    }
    #pragma unroll
    for (int s = 16; s; s >>= 1) acc += __shfl_xor_sync(0xffffffffu, acc, s);
    if (lane == 0) out[b] = (acc + lb[0]) * ow[0] + ob[0];
}

// ---------------- CIN fp8, software-pipelined: cp.async W (dist 2, 3-buf), ------
// ---------------- double-buffered P, one barrier per chunk ----------------------
__global__ __launch_bounds__(256, 2) void cin_fp8(const float* __restrict__ b1,
                                                  const float* __restrict__ b2,
                                                  const float* __restrict__ ow,
                                                  float* __restrict__ out) {
    extern __shared__ char smem[];
    const unsigned sbase = smem_u32(smem);
    float*          red  = (float*)(smem + OFF_RED);
    float*          b1s  = (float*)(smem + OFF_B1);
    float*          b2s  = (float*)(smem + OFF_B2);
    float*          ow1v = (float*)(smem + OFF_OW1);
    float*          ow2v = (float*)(smem + OFF_OW2);
    unsigned*       hmw  = (unsigned*)(smem + OFF_HM);
    float*          x0s  = (float*)(smem + OFF_X0);
    float*          nxts = (float*)(smem + OFF_NXT);

    const int tid = threadIdx.x, wid = tid >> 5, lane = tid & 31;
    const int wm = wid >> 1, wn = wid & 1;          // 4 M-warps x 2 N-warps
    const int gid = lane >> 2, tig = lane & 3;
    const int b0 = blockIdx.x * 8;

    {   // stage inputs; x0 scaled by 2^9 for fp8 range
        const float4* src = (const float4*)&g_flat[(size_t)b0 * IN_DIM];
        float4* dst = (float4*)x0s;
        for (int j = tid; j < 8 * IN_DIM / 4; j += 256) {
            float4 v = src[j];
            v.x *= 512.f; v.y *= 512.f; v.z *= 512.f; v.w *= 512.f;
            dst[j] = v;
        }
        for (int j = tid; j < T1P; j += 256) hmw[j] = g_hm1[j];
        if (tid < 128) { b1s[tid] = b1[tid]; b2s[tid] = b2[tid]; ow2v[tid] = ow[65 + tid]; }
        if (tid < 64) ow1v[tid] = ow[1 + tid];
        if (tid < 8) red[tid] = 0.f;
    }

    const int row = tid >> 1, half = tid & 1;       // P-build mapping: 2 threads per row
    const int bb = row >> 4, dd = row & 15;
    const float* xb = x0s + bb * IN_DIM + dd;       // element at xb[h*16]

    // ldmatrix lane address offset within a P buffer
    const int mi = lane >> 3, r7 = lane & 7;
    const unsigned rowsel = (unsigned)((wm * 32 + (mi & 1) * 8 + r7) * 80 + (mi >> 1) * 16);
    const unsigned pbase[2] = { sbase + OFF_P0 + rowsel, sbase + OFF_P1 + rowsel };
    char* const   pdst[2]  = { smem + OFF_P0 + row * 80 + half * 32,
                               smem + OFF_P1 + row * 80 + half * 32 };
    const unsigned wbase = sbase + OFF_W;

    float acc[2][8][4];

    // ---- pipeline primitives ----
    auto prefW = [&](const uint4* chunk_src, int g) {
        unsigned dst = wbase + (unsigned)(g % 3) * 8192u + (unsigned)tid * 16u;
        cp_async16(dst, chunk_src + tid);
        cp_async16(dst + 4096u, chunk_src + 256 + tid);
        CP_COMMIT();
    };
    auto buildP1 = [&](int c, char* dst) {
        int tb = c * 64 + half * 32;
        unsigned u[8];
        #pragma unroll
        for (int g = 0; g < 8; g++) {
            unsigned m0 = hmw[tb + 4 * g],     m1 = hmw[tb + 4 * g + 1];
            unsigned m2 = hmw[tb + 4 * g + 2], m3 = hmw[tb + 4 * g + 3];
            u[g] = pk_e4m3x4(xb[m0 & 0xffff] * xb[m0 >> 16],
                             xb[m1 & 0xffff] * xb[m1 >> 16],
                             xb[m2 & 0xffff] * xb[m2 >> 16],
                             xb[m3 & 0xffff] * xb[m3 >> 16]);
        }
        ((uint4*)dst)[0] = make_uint4(u[0], u[1], u[2], u[3]);
        ((uint4*)dst)[1] = make_uint4(u[4], u[5], u[6], u[7]);
    };
    const float* nr = nxts + row * 68 + half * 32;
    auto buildP2 = [&](int c2, char* dst) {
        float xv = x0s[bb * IN_DIM + c2 * 16 + dd];
        unsigned u[8];
        #pragma unroll
        for (int g = 0; g < 8; g++) {
            float4 nv = *(const float4*)(nr + 4 * g);
            u[g] = pk_e4m3x4(nv.x * xv, nv.y * xv, nv.z * xv, nv.w * xv);
        }
        ((uint4*)dst)[0] = make_uint4(u[0], u[1], u[2], u[3]);
        ((uint4*)dst)[1] = make_uint4(u[4], u[5], u[6], u[7]);
    };
    auto mmaChunk = [&](int g) {
        const uint2* Wc2 = (const uint2*)(smem + OFF_W + (g % 3) * 8192);
        unsigned pb = pbase[g & 1];
        #pragma unroll
        for (int ks = 0; ks < 2; ks++) {
            unsigned bf[8][2];
            #pragma unroll
            for (int nf = 0; nf < 8; nf++) {
                uint2 w = Wc2[(ks * 16 + wn * 8 + nf) * 32 + lane];
                bf[nf][0] = w.x; bf[nf][1] = w.y;
            }
            #pragma unroll
            for (int fm = 0; fm < 2; fm++) {
                unsigned a0, a1, a2, a3;
                ldm4(a0, a1, a2, a3, pb + (unsigned)(fm * 16 * 80 + ks * 32));
                #pragma unroll
                for (int nf = 0; nf < 8; nf++)
                    mma_fp8(acc[fm][nf], a0, a1, a2, a3, bf[nf][0], bf[nf][1]);
            }
        }
    };

    // ---- preload W(0), W(1); staging must be visible before P build reads x0s ----
    prefW(g_W1f4, 0);
    prefW(g_W1f4 + 512, 1);
    __syncthreads();          // x0s/hmw staging visible
    buildP1(0, pdst[0]);
    CP_WAIT1();               // W(0) complete
    __syncthreads();          // P(0) visible

    // ================= LAYER 1 (g = 0..12) =================
    #pragma unroll
    for (int fm = 0; fm < 2; fm++)
        #pragma unroll
        for (int nf = 0; nf < 8; nf++)
            #pragma unroll
            for (int q = 0; q < 4; q++) acc[fm][nf][q] = 0.f;

    for (int c = 0; c < NCH1; c++) {
        mmaChunk(c);
        if (c < NCH1 - 1) buildP1(c + 1, pdst[(c + 1) & 1]);
        {   // prefetch g=c+2 (spills into layer-2 chunks 0,1)
            int g2 = c + 2;
            if (g2 < NCH1) prefW(g_W1f4 + g2 * 512, g2);
            else prefW(g_W2f4 + (g2 - NCH1) * 512, g2);
        }
        CP_WAIT1();
        __syncthreads();
    }

    // ---- layer-1 epilogue: cols 0..63 -> nxt (f32 scaled 2^17); 64..127 -> hi1 dot ----
    if (wn == 0) {
        #pragma unroll
        for (int fm = 0; fm < 2; fm++) {
            int r0 = wm * 32 + fm * 16 + gid;
            #pragma unroll
            for (int nf = 0; nf < 8; nf++) {
                int o0 = nf * 8 + tig * 2;
                nxts[r0 * 68 + o0]           = fmaxf(acc[fm][nf][0] * S1INV + b1s[o0], 0.f) * SNXT;
                nxts[r0 * 68 + o0 + 1]       = fmaxf(acc[fm][nf][1] * S1INV + b1s[o0 + 1], 0.f) * SNXT;
                nxts[(r0 + 8) * 68 + o0]     = fmaxf(acc[fm][nf][2] * S1INV + b1s[o0], 0.f) * SNXT;
                nxts[(r0 + 8) * 68 + o0 + 1] = fmaxf(acc[fm][nf][3] * S1INV + b1s[o0 + 1], 0.f) * SNXT;
            }
        }
    } else {
        #pragma unroll
        for (int fm = 0; fm < 2; fm++) {
            float s = 0.f;
            #pragma unroll
            for (int nf = 0; nf < 8; nf++) {
                int oo = nf * 8 + tig * 2;          // global o = 64+oo
                s += fmaxf(acc[fm][nf][0] * S1INV + b1s[64 + oo], 0.f) * ow1v[oo];
                s += fmaxf(acc[fm][nf][1] * S1INV + b1s[64 + oo + 1], 0.f) * ow1v[oo + 1];
                s += fmaxf(acc[fm][nf][2] * S1INV + b1s[64 + oo], 0.f) * ow1v[oo];
                s += fmaxf(acc[fm][nf][3] * S1INV + b1s[64 + oo + 1], 0.f) * ow1v[oo + 1];
            }
            #pragma unroll
            for (int sh = 16; sh; sh >>= 1) s += __shfl_xor_sync(0xffffffffu, s, sh);
            if (lane == 0) atomicAdd(&red[wm * 2 + fm], s);
        }
    }
    __syncthreads();          // nxts visible

    // ================= LAYER 2 (g = 13..51; chunk c2 == x0 field m) =================
    #pragma unroll
    for (int fm = 0; fm < 2; fm++)
        #pragma unroll
        for (int nf = 0; nf < 8; nf++)
            #pragma unroll
            for (int q = 0; q < 4; q++) acc[fm][nf][q] = 0.f;

    buildP2(0, pdst[NCH1 & 1]);
    __syncthreads();          // P2(0) visible; W(13) completed during layer-1 tail

    for (int c2 = 0; c2 < NCH2; c2++) {
        int g = NCH1 + c2;
        mmaChunk(g);
        if (c2 < NCH2 - 1) buildP2(c2 + 1, pdst[(g + 1) & 1]);
        if (c2 + 2 < NCH2) prefW(g_W2f4 + (c2 + 2) * 512, g + 2);
        else CP_COMMIT();     // keep the group count flowing for WAIT1
        CP_WAIT1();
        __syncthreads();
    }

    // ---- layer-2 epilogue: relu + dot ow[65..193) ----
    #pragma unroll
    for (int fm = 0; fm < 2; fm++) {
        float s = 0.f;
        #pragma unroll
        for (int nf = 0; nf < 8; nf++) {
            int o = wn * 64 + nf * 8 + tig * 2;
            s += fmaxf(acc[fm][nf][0] * S2INV + b2s[o], 0.f) * ow2v[o];
            s += fmaxf(acc[fm][nf][1] * S2INV + b2s[o + 1], 0.f) * ow2v[o + 1];
            s += fmaxf(acc[fm][nf][2] * S2INV + b2s[o], 0.f) * ow2v[o];
            s += fmaxf(acc[fm][nf][3] * S2INV + b2s[o + 1], 0.f) * ow2v[o + 1];
        }
        #pragma unroll
        for (int sh = 16; sh; sh >>= 1) s += __shfl_xor_sync(0xffffffffu, s, sh);
        if (lane == 0) atomicAdd(&red[wm * 2 + fm], s);
    }
    __syncthreads();
    if (tid < 8) atomicAdd(&out[b0 + tid], red[tid]);
}

// ---------------- deep-tower GEMM (64x64 tile, BN-on-load, stats epilogue) ----------------
__global__ __launch_bounds__(256) void gemm_deep(const float* __restrict__ A, int lda,
                                                 const float* __restrict__ B, int ldb,
                                                 const float* __restrict__ bias,
                                                 float* __restrict__ C, int K, int N,
                                                 int use_bn, const float* __restrict__ statsIn,
                                                 const float* __restrict__ bng,
                                                 const float* __restrict__ bnb,
                                                 float* __restrict__ statsOut) {
    __shared__ float As[16][68];
    __shared__ float Bs[16][68];
    __shared__ float bnsc[D1], bnsh[D1];

    int tx = threadIdx.x & 15, ty = threadIdx.x >> 4;
    int m0 = blockIdx.y * 64, n0 = blockIdx.x * 64;

    if (use_bn) {
        for (int k = threadIdx.x; k < K; k += 256) {
            float mean = statsIn[k] * (1.f / BATCH);
            float var  = statsIn[400 + k] * (1.f / BATCH) - mean * mean;
            float sc = bng[k] * rsqrtf(var + BN_EPS);
            bnsc[k] = sc; bnsh[k] = bnb[k] - mean * sc;
        }
        __syncthreads();
    }

    float accr[4][4];
    #pragma unroll
    for (int i = 0; i < 4; i++)
        #pragma unroll
        for (int j = 0; j < 4; j++) accr[i][j] = 0.f;

    for (int k0 = 0; k0 < K; k0 += 16) {
        {
            int rw = threadIdx.x >> 2;
            int kq = (threadIdx.x & 3) * 4;
            float4 v = *(const float4*)&A[(size_t)(m0 + rw) * lda + k0 + kq];
            if (use_bn) {
                v.x = fmaxf(v.x * bnsc[k0 + kq + 0] + bnsh[k0 + kq + 0], 0.f);
                v.y = fmaxf(v.y * bnsc[k0 + kq + 1] + bnsh[k0 + kq + 1], 0.f);
                v.z = fmaxf(v.z * bnsc[k0 + kq + 2] + bnsh[k0 + kq + 2], 0.f);
                v.w = fmaxf(v.w * bnsc[k0 + kq + 3] + bnsh[k0 + kq + 3], 0.f);
            }
            As[kq + 0][rw] = v.x; As[kq + 1][rw] = v.y;
            As[kq + 2][rw] = v.z; As[kq + 3][rw] = v.w;
        }
        {
            int kk = threadIdx.x >> 4;
            int nq = (threadIdx.x & 15) * 4;
            int n  = n0 + nq;
            float4 v = make_float4(0.f, 0.f, 0.f, 0.f);
            if (n < N) v = *(const float4*)&B[(size_t)(k0 + kk) * ldb + n];
            *(float4*)&Bs[kk][nq] = v;
        }
        __syncthreads();
        #pragma unroll
        for (int kk = 0; kk < 16; kk++) {
            float4 a  = *(const float4*)&As[kk][ty * 4];
            float4 bv = *(const float4*)&Bs[kk][tx * 4];
            float al[4] = {a.x, a.y, a.z, a.w};
            float bl[4] = {bv.x, bv.y, bv.z, bv.w};
            #pragma unroll
            for (int i = 0; i < 4; i++)
                #pragma unroll
                for (int j = 0; j < 4; j++) accr[i][j] += al[i] * bl[j];
        }
        __syncthreads();
    }

    float colsum[4] = {0.f, 0.f, 0.f, 0.f};
    float colsq[4]  = {0.f, 0.f, 0.f, 0.f};
    #pragma unroll
    for (int j = 0; j < 4; j++) {
        int n = n0 + tx * 4 + j;
        float bj = (n < N) ? bias[n] : 0.f;
        #pragma unroll
        for (int i = 0; i < 4; i++) {
            int rw = m0 + ty * 4 + i;
            float v = accr[i][j] + bj;
            if (n < N) C[(size_t)rw * N + n] = v;
            colsum[j] += v;
            colsq[j]  += v * v;
        }
    }
    __syncthreads();
    #pragma unroll
    for (int j = 0; j < 4; j++) As[ty][tx * 4 + j] = colsum[j];
    __syncthreads();
    if (threadIdx.x < 64) {
        float s = 0.f;
        #pragma unroll
        for (int r = 0; r < 16; r++) s += As[r][threadIdx.x];
        int n = n0 + threadIdx.x;
        if (n < N) atomicAdd(&statsOut[n], s);
    }
    __syncthreads();
    #pragma unroll
    for (int j = 0; j < 4; j++) As[ty][tx * 4 + j] = colsq[j];
    __syncthreads();
    if (threadIdx.x < 64) {
        float s = 0.f;
        #pragma unroll
        for (int r = 0; r < 16; r++) s += As[r][threadIdx.x];
        int n = n0 + threadIdx.x;
        if (n < N) atomicAdd(&statsOut[400 + n], s);
    }
}

// ---------------- final: BN2 + relu + dot with out_w deep segment ----------------
__global__ void final_deep(const float* __restrict__ bng2, const float* __restrict__ bnb2,
                           const float* __restrict__ ow, float* __restrict__ out) {
    __shared__ float sc[D2], sh[D2];
    for (int k = threadIdx.x; k < D2; k += 256) {
        float mean = g_stats[800 + k] * (1.f / BATCH);
        float var  = g_stats[1200 + k] * (1.f / BATCH) - mean * mean;
        float s = bng2[k] * rsqrtf(var + BN_EPS);
        sc[k] = s; sh[k] = bnb2[k] - mean * s;
    }
    __syncthreads();
    int b    = blockIdx.x * 8 + (threadIdx.x >> 5);
    int lane = threadIdx.x & 31;
    float acc = 0.f;
    for (int k = lane; k < D2; k += 32) {
        float v = fmaxf(g_z2[b * D2 + k] * sc[k] + sh[k], 0.f);
        acc += v * ow[1 + 192 + k];
    }
    #pragma unroll
    for (int s = 16; s; s >>= 1) acc += __shfl_xor_sync(0xffffffffu, acc, s);
    if (lane == 0) atomicAdd(&out[b], acc);
}

// ---------------- launcher: single stream (graph-capture safe) ----------------
extern "C" void kernel_launch(void* const* d_in, const int* in_sizes, int n_in,
                              void* d_out, int out_size) {
    const int*   fi  = (const int*)  d_in[0];
    const float* emb = (const float*)d_in[2];
    const float* lw  = (const float*)d_in[3];
    const float* lb  = (const float*)d_in[4];
    const float* w1  = (const float*)d_in[5];
    const float* cb1 = (const float*)d_in[6];
    const float* w2  = (const float*)d_in[7];
    const float* cb2 = (const float*)d_in[8];
    const float* dw1 = (const float*)d_in[9];
    const float* db1 = (const float*)d_in[10];
    const float* bg1 = (const float*)d_in[11];
    const float* bb1 = (const float*)d_in[12];
    const float* dw2 = (const float*)d_in[13];
    const float* db2 = (const float*)d_in[14];
    const float* bg2 = (const float*)d_in[15];
    const float* bb2 = (const float*)d_in[16];
    const float* ow  = (const float*)d_in[17];
    const float* ob  = (const float*)d_in[18];
    float* out = (float*)d_out;

    float* z1p; cudaGetSymbolAddress((void**)&z1p, g_z1);
    float* z2p; cudaGetSymbolAddress((void**)&z2p, g_z2);
    float* flatp; cudaGetSymbolAddress((void**)&flatp, g_flat);
    float* statsp; cudaGetSymbolAddress((void**)&statsp, g_stats);

    cudaFuncSetAttribute(cin_fp8, cudaFuncAttributeMaxDynamicSharedMemorySize, CIN_SM);

    prep_hm<<<1, 32>>>();
    prep_w1f<<<(NCH1 * 1024 + 255) / 256, 256>>>(w1);
    prep_w2f<<<(NCH2 * 1024 + 255) / 256, 256>>>(w2);
    zero_stats<<<7, 256>>>();

    gather_linear<<<BATCH / 8, 256>>>(fi, emb, lw, lb, ow, ob, out);

    cin_fp8<<<BATCH / 8, 256, CIN_SM>>>(cb1, cb2, ow, out);

    gemm_deep<<<dim3((D1 + 63) / 64, BATCH / 64), 256>>>(
        flatp, IN_DIM, dw1, D1, db1, z1p, IN_DIM, D1,
        0, nullptr, nullptr, nullptr, statsp);

    gemm_deep<<<dim3((D2 + 63) / 64, BATCH / 64), 256>>>(
        z1p, D1, dw2, D2, db2, z2p, D1, D2,
        1, statsp, bg1, bb1, statsp + 800);

    final_deep<<<BATCH / 8, 256>>>(bg2, bb2, ow, out);
}